// round 7
// baseline (speedup 1.0000x reference)
#include <cuda_runtime.h>

#define NATOMS 512
#define BATCH  32
#define NN     (NATOMS * NATOMS)
#define INV2PI 0.15915494309189535f
#define NT     16
#define NTILES (NT * (NT + 1) / 2)   // 136

typedef unsigned long long u64;

struct F3 { float x, y, z; };

__device__ __forceinline__ F3 f3sub(float4 a, float4 b) { return {a.x - b.x, a.y - b.y, a.z - b.z}; }
__device__ __forceinline__ F3 f3cross(F3 a, F3 b) {
    return {a.y * b.z - a.z * b.y,
            a.z * b.x - a.x * b.z,
            a.x * b.y - a.y * b.x};
}
__device__ __forceinline__ float f3dot(F3 a, F3 b) { return a.x * b.x + a.y * b.y + a.z * b.z; }

__device__ __forceinline__ float rsqrt_a(float x) {
    float r; asm("rsqrt.approx.f32 %0, %1;" : "=f"(r) : "f"(x)); return r;
}
__device__ __forceinline__ float sqrt_a(float x) {
    float r; asm("sqrt.approx.f32 %0, %1;" : "=f"(r) : "f"(x)); return r;
}

// ---- packed f32x2 helpers (non-volatile: CSE-able) ----
__device__ __forceinline__ u64 pk2(float lo, float hi) {
    u64 r; asm("mov.b64 %0, {%1, %2};" : "=l"(r) : "f"(lo), "f"(hi)); return r;
}
__device__ __forceinline__ void upk2(u64 v, float& lo, float& hi) {
    asm("mov.b64 {%0, %1}, %2;" : "=f"(lo), "=f"(hi) : "l"(v));
}
__device__ __forceinline__ u64 fma2(u64 a, u64 b, u64 c) {
    u64 d; asm("fma.rn.f32x2 %0, %1, %2, %3;" : "=l"(d) : "l"(a), "l"(b), "l"(c)); return d;
}
__device__ __forceinline__ u64 mul2(u64 a, u64 b) {
    u64 d; asm("mul.rn.f32x2 %0, %1, %2;" : "=l"(d) : "l"(a), "l"(b)); return d;
}
__device__ __forceinline__ u64 add2(u64 a, u64 b) {
    u64 d; asm("add.rn.f32x2 %0, %1, %2;" : "=l"(d) : "l"(a), "l"(b)); return d;
}

struct PV { u64 x, y, z; };   // packed pair of float3s (lane0, lane1)

__device__ __forceinline__ PV pvpack(F3 lo, F3 hi) {
    return { pk2(lo.x, hi.x), pk2(lo.y, hi.y), pk2(lo.z, hi.z) };
}
__device__ __forceinline__ PV pvneg(PV a, u64 n1) {
    return { mul2(a.x, n1), mul2(a.y, n1), mul2(a.z, n1) };
}
// cross2(a, b) with nb = -b available: a x b per lane.
__device__ __forceinline__ PV cross2(PV a, PV b, PV nb) {
    return { fma2(a.z, nb.y, mul2(a.y, b.z)),
             fma2(a.x, nb.z, mul2(a.z, b.x)),
             fma2(a.y, nb.x, mul2(a.x, b.y)) };
}
__device__ __forceinline__ u64 dot2(PV a, PV b) {
    return fma2(a.z, b.z, fma2(a.y, b.y, mul2(a.x, b.x)));
}

// Paired asin via A&S 4.4.46 (|err|<=2e-8): asin(t) = pi/2 - sqrt(1-t)*P7(t).
__device__ __forceinline__ void asin2_fast(float xa, float xb, float& ra, float& rb) {
    float ta = fminf(fabsf(xa), 1.0f);
    float tb = fminf(fabsf(xb), 1.0f);
    float sa = 1.0f - ta;
    float sb = 1.0f - tb;

    u64 t2 = pk2(ta, tb);
    u64 p  = pk2(-0.0012624911f, -0.0012624911f);
    p = fma2(p, t2, pk2( 0.0066700901f,  0.0066700901f));
    p = fma2(p, t2, pk2(-0.0170881256f, -0.0170881256f));
    p = fma2(p, t2, pk2( 0.0308918810f,  0.0308918810f));
    p = fma2(p, t2, pk2(-0.0501743046f, -0.0501743046f));
    p = fma2(p, t2, pk2( 0.0889789874f,  0.0889789874f));
    p = fma2(p, t2, pk2(-0.2145988016f, -0.2145988016f));
    p = fma2(p, t2, pk2( 1.5707963050f,  1.5707963050f));

    float pa, pb;
    upk2(p, pa, pb);
    float qa = fmaf(sqrt_a(sa), -pa, 1.5707963267948966f);
    float qb = fmaf(sqrt_a(sb), -pb, 1.5707963267948966f);
    ra = copysignf(qa, xa);
    rb = copysignf(qb, xb);
}

// Chain A cell finish: d01,d12 true; m23 = -(u2.u3); m30 = -(u3.u0); sva = u0.e2
// (true sv = -sva). omega = a01+a12-(asin(m23 r2r3)+asin(m30 r3r0)).
__device__ __forceinline__ float finishA(
    float d01, float d12, float m23, float m30,
    float r0, float r1, float r2, float r3, float sva)
{
    float t01 = d01 * (r0 * r1);
    float t12 = d12 * (r1 * r2);
    float t23 = m23 * (r2 * r3);
    float t30 = m30 * (r3 * r0);
    float a, b, c, d;
    asin2_fast(t01, t12, a, b);
    asin2_fast(t23, t30, c, d);
    float om = ((a + b) - (c + d)) * INV2PI;
    unsigned sm = (__float_as_uint(sva) ^ 0x80000000u) & 0x80000000u;
    return __uint_as_float(__float_as_uint(om) ^ sm);
}

// Chain B cell finish: u0 = -U2A folded. m01 = U2A.U1B = -(u0.u1);
// d12,d23 true; m30 = U3B.U2A = -(u3.u0); svb = U2A.E2B = +true sv.
__device__ __forceinline__ float finishB(
    float m01, float d12, float d23, float m30,
    float r0, float r1, float r2, float r3, float svb)
{
    float t12 = d12 * (r1 * r2);
    float t23 = d23 * (r2 * r3);
    float t01 = m01 * (r0 * r1);
    float t30 = m30 * (r3 * r0);
    float a, b, c, d;
    asin2_fast(t12, t23, a, b);
    asin2_fast(t01, t30, c, d);
    float om = ((a + b) - (c + d)) * INV2PI;
    unsigned sm = __float_as_uint(svb) & 0x80000000u;
    return __uint_as_float(__float_as_uint(om) ^ sm);
}

// Segment set: {(i,j): 0<=i<=509, i+2<=j<=510}. Final scatter state:
// every (i,j) owns out[i+1][j+1] (+mirror); i==0 also keeps out[0][j] (+mirror).
// Never-written cells (|r-c|<=1 band, (0,511),(511,0)) zeroed by diagonal tiles.
//
// Math per cell (g = x[j+1]-x[j]):
//   e0 = P2-x[i], e2 = P2-x[i+1];  u0 = e0 x g, u2 = g x e2, u3 = e2 x e0,
//   u1 = u0+u2-u3;  t_ab = (ua.ub) ra rb;  omega = sum asin(t);
//   wr = omega * sign(-(u0.e2)) / 2pi.
// Identities used: e0(k+1)=e2(k); u0(k+1)=-u2(k); r0(k+1)=r2(k).
// Chains A={cells 0,2}, B={cells 1,3}: U0B=-U2A, E0B=E2A (zero lane mixing).
__global__ __launch_bounds__(256) void writhe_tile_kernel(
    const float* __restrict__ x,
    float*       __restrict__ out)
{
    __shared__ float4 si[33];
    __shared__ float4 sj4[33];
    __shared__ float  smwr[32][33];

    int k = blockIdx.x, ti = 0;
    while (k >= NT - ti) { k -= NT - ti; ti++; }
    const int tj = ti + k;
    const int i0 = ti * 32, j0 = tj * 32;
    const bool fastTile = (ti >= 1) && (tj >= ti + 2) && (tj <= 14);

    const int b = blockIdx.y;
    const float* xb = x + (size_t)b * (NATOMS * 3);
    float* ob = out + (size_t)b * NN;

    const int tx = threadIdx.x & 31;
    const int ty = threadIdx.x >> 5;

    {
        int t = threadIdx.x;
        if (t < 66) {
            int local = (t < 33) ? t : t - 33;
            int c = min(((t < 33) ? i0 : j0) + local, NATOMS - 1);
            float4 v = make_float4(xb[3 * c], xb[3 * c + 1], xb[3 * c + 2], 0.f);
            if (t < 33) si[local] = v; else sj4[local] = v;
        }
    }
    if (ty == 1 && ti == tj) {
        int r = i0 + tx;
        ob[r * 513] = 0.f;
        if (r < NATOMS - 1) { ob[r * 513 + 1] = 0.f; ob[r * 513 + 512] = 0.f; }
        if (ti == 0 && tx == 0) { ob[NATOMS - 1] = 0.f; ob[(NATOMS - 1) * NATOMS] = 0.f; }
    }
    __syncthreads();

    const int j = j0 + tx;
    const float4 Q2 = sj4[tx];
    const float4 Q3 = sj4[tx + 1];
    const F3 g = f3sub(Q3, Q2);
    const F3 p2 = { Q2.x, Q2.y, Q2.z };

    const int ibase = 4 * ty;
    const float4 A0 = si[ibase];
    const float4 A1 = si[ibase + 1];
    const float4 A2 = si[ibase + 2];
    const float4 A3 = si[ibase + 3];
    const float4 A4 = si[ibase + 4];

    const u64 N1 = pk2(-1.0f, -1.0f);
    const PV G   = pvpack(g, g);
    const PV P2p = pvpack(p2, p2);

    // e2 per cell, chains A=(0,2), B=(1,3):  e2(k) = P2 - x[i_k+1]
    PV P1A = pvpack({A1.x, A1.y, A1.z}, {A3.x, A3.y, A3.z});
    PV P1B = pvpack({A2.x, A2.y, A2.z}, {A4.x, A4.y, A4.z});
    PV E2A = { fma2(P1A.x, N1, P2p.x), fma2(P1A.y, N1, P2p.y), fma2(P1A.z, N1, P2p.z) };
    PV E2B = { fma2(P1B.x, N1, P2p.x), fma2(P1B.y, N1, P2p.y), fma2(P1B.z, N1, P2p.z) };
    PV NE2A = pvneg(E2A, N1);
    PV NE2B = pvneg(E2B, N1);

    PV U2A = cross2(G, E2A, NE2A);      // true u2 (cells 0,2)
    PV U2B = cross2(G, E2B, NE2B);      // true u2 (cells 1,3)

    // Fresh cell-0 u0 (scalar)
    F3 e00 = f3sub(Q2, A0);
    F3 u00 = f3cross(e00, g);
    float n00 = f3dot(u00, u00);

    // Lane-mix: E0A = (e0(0), e2(1));  U0A = (u0(0), -u2(1))
    float e2b_lx, e2b_hx, e2b_ly, e2b_hy, e2b_lz, e2b_hz;
    upk2(E2B.x, e2b_lx, e2b_hx);
    upk2(E2B.y, e2b_ly, e2b_hy);
    upk2(E2B.z, e2b_lz, e2b_hz);
    float u2b_lx, u2b_hx, u2b_ly, u2b_hy, u2b_lz, u2b_hz;
    upk2(U2B.x, u2b_lx, u2b_hx);
    upk2(U2B.y, u2b_ly, u2b_hy);
    upk2(U2B.z, u2b_lz, u2b_hz);

    PV E0A = { pk2(e00.x, e2b_lx), pk2(e00.y, e2b_ly), pk2(e00.z, e2b_lz) };
    PV U0A = { pk2(u00.x, -u2b_lx), pk2(u00.y, -u2b_ly), pk2(u00.z, -u2b_lz) };

    PV T3A = cross2(E0A, E2A, NE2A);    // = e0 x e2 = -u3  (chain A)
    PV U3B = cross2(E2B, E2A, NE2A);    // = e2 x e0 = true u3 (chain B; E0B=E2A)

    // u1 = u0 + u2 - u3:  chain A: U0A + U2A + T3A;  chain B: U2B - U2A - U3B
    PV U1A = { add2(add2(U0A.x, U2A.x), T3A.x),
               add2(add2(U0A.y, U2A.y), T3A.y),
               add2(add2(U0A.z, U2A.z), T3A.z) };
    PV U1B = { fma2(U3B.x, N1, fma2(U2A.x, N1, U2B.x)),
               fma2(U3B.y, N1, fma2(U2A.y, N1, U2B.y)),
               fma2(U3B.z, N1, fma2(U2A.z, N1, U2B.z)) };

    // Packed norms and dots
    u64 q2A = dot2(U2A, U2A), q2B = dot2(U2B, U2B);
    u64 q1A = dot2(U1A, U1A), q1B = dot2(U1B, U1B);
    u64 q3A = dot2(T3A, T3A), q3B = dot2(U3B, U3B);

    u64 D01A = dot2(U0A, U1A), M01B = dot2(U2A, U1B);
    u64 D12A = dot2(U1A, U2A), D12B = dot2(U1B, U2B);
    u64 M23A = dot2(U2A, T3A), D23B = dot2(U2B, U3B);
    u64 M30A = dot2(T3A, U0A), M30B = dot2(U3B, U2A);
    u64 SVA  = dot2(U0A, E2A), SVB  = dot2(U2A, E2B);

    float n2_0, n2_2, n2_1, n2_3, n1_0, n1_2, n1_1, n1_3, n3_0, n3_2, n3_1, n3_3;
    upk2(q2A, n2_0, n2_2); upk2(q2B, n2_1, n2_3);
    upk2(q1A, n1_0, n1_2); upk2(q1B, n1_1, n1_3);
    upk2(q3A, n3_0, n3_2); upk2(q3B, n3_1, n3_3);

    float r0_0 = rsqrt_a(n00);
    float r2_0 = rsqrt_a(n2_0), r2_1 = rsqrt_a(n2_1), r2_2 = rsqrt_a(n2_2), r2_3 = rsqrt_a(n2_3);
    float r1_0 = rsqrt_a(n1_0), r1_1 = rsqrt_a(n1_1), r1_2 = rsqrt_a(n1_2), r1_3 = rsqrt_a(n1_3);
    float r3_0 = rsqrt_a(n3_0), r3_1 = rsqrt_a(n3_1), r3_2 = rsqrt_a(n3_2), r3_3 = rsqrt_a(n3_3);

    float d01_0, d01_2, m01_1, m01_3, d12_0, d12_2, d12_1, d12_3;
    float m23_0, m23_2, d23_1, d23_3, m30_0, m30_2, m30_1, m30_3, sv_0, sv_2, sv_1, sv_3;
    upk2(D01A, d01_0, d01_2); upk2(M01B, m01_1, m01_3);
    upk2(D12A, d12_0, d12_2); upk2(D12B, d12_1, d12_3);
    upk2(M23A, m23_0, m23_2); upk2(D23B, d23_1, d23_3);
    upk2(M30A, m30_0, m30_2); upk2(M30B, m30_1, m30_3);
    upk2(SVA,  sv_0,  sv_2);  upk2(SVB,  sv_1,  sv_3);

    float wrv[4];
    // r0 carry: r0(1)=r2(0); r0(2)=r2(1); r0(3)=r2(2)
    wrv[0] = finishA(d01_0, d12_0, m23_0, m30_0, r0_0, r1_0, r2_0, r3_0, sv_0);
    wrv[1] = finishB(m01_1, d12_1, d23_1, m30_1, r2_0, r1_1, r2_1, r3_1, sv_1);
    wrv[2] = finishA(d01_2, d12_2, m23_2, m30_2, r2_1, r1_2, r2_2, r3_2, sv_2);
    wrv[3] = finishB(m01_3, d12_3, d23_3, m30_3, r2_2, r1_3, r2_3, r3_3, sv_3);

    #pragma unroll
    for (int kk = 0; kk < 4; kk++)
        smwr[ibase + kk][tx] = wrv[kk];

    if (fastTile) {
        float* orow = ob + (size_t)(i0 + ibase + 1) * NATOMS + (j + 1);
        #pragma unroll
        for (int kk = 0; kk < 4; kk++)
            orow[kk * NATOMS] = wrv[kk];
    } else {
        #pragma unroll
        for (int kk = 0; kk < 4; kk++) {
            const int i = i0 + ibase + kk;
            bool valid = (j >= i + 2) && (i <= NATOMS - 3) && (j <= NATOMS - 2);
            if (valid) {
                ob[(i + 1) * NATOMS + (j + 1)] = wrv[kk];
                if (i == 0) {
                    ob[j] = wrv[kk];
                    ob[j * NATOMS] = wrv[kk];
                }
            }
        }
    }
    __syncthreads();

    // Mirror: coalesced out[j+1][i+1] via transposed smem reads (stride 33).
    if (fastTile) {
        float* ocol = ob + (size_t)(j0 + ibase + 1) * NATOMS + (i0 + tx + 1);
        #pragma unroll
        for (int kk = 0; kk < 4; kk++)
            ocol[kk * NATOMS] = smwr[tx][ibase + kk];
    } else {
        #pragma unroll
        for (int kk = 0; kk < 4; kk++) {
            const int jj = ibase + kk;
            const int jm = j0 + jj;
            const int im = i0 + tx;
            float v = smwr[tx][jj];
            bool valid = (jm >= im + 2) && (im <= NATOMS - 3) && (jm <= NATOMS - 2);
            if (valid)
                ob[(jm + 1) * NATOMS + (im + 1)] = v;
        }
    }
}

extern "C" void kernel_launch(void* const* d_in, const int* in_sizes, int n_in,
                              void* d_out, int out_size)
{
    int xi = (in_sizes[0] == BATCH * NATOMS * 3) ? 0 : 1;
    const float* x   = (const float*)d_in[xi];
    float*       out = (float*)d_out;

    dim3 grid(NTILES, BATCH);
    writhe_tile_kernel<<<grid, 256>>>(x, out);
}

// round 8
// speedup vs baseline: 1.0708x; 1.0708x over previous
#include <cuda_runtime.h>

#define NATOMS 512
#define BATCH  32
#define NN     (NATOMS * NATOMS)
#define INV2PI 0.15915494309189535f
#define NT     16
#define NTILES (NT * (NT + 1) / 2)   // 136

typedef unsigned long long u64;

struct F3 { float x, y, z; };

__device__ __forceinline__ F3 f3sub(float4 a, float4 b) { return {a.x - b.x, a.y - b.y, a.z - b.z}; }
__device__ __forceinline__ F3 f3cross(F3 a, F3 b) {
    return {a.y * b.z - a.z * b.y,
            a.z * b.x - a.x * b.z,
            a.x * b.y - a.y * b.x};
}
__device__ __forceinline__ float f3dot(F3 a, F3 b) { return a.x * b.x + a.y * b.y + a.z * b.z; }

__device__ __forceinline__ float rsqrt_a(float x) {
    float r; asm("rsqrt.approx.f32 %0, %1;" : "=f"(r) : "f"(x)); return r;
}
__device__ __forceinline__ float sqrt_a(float x) {
    float r; asm("sqrt.approx.f32 %0, %1;" : "=f"(r) : "f"(x)); return r;
}

// ---- packed f32x2 helpers (non-volatile: CSE-able) ----
__device__ __forceinline__ u64 pk2(float lo, float hi) {
    u64 r; asm("mov.b64 %0, {%1, %2};" : "=l"(r) : "f"(lo), "f"(hi)); return r;
}
__device__ __forceinline__ void upk2(u64 v, float& lo, float& hi) {
    asm("mov.b64 {%0, %1}, %2;" : "=f"(lo), "=f"(hi) : "l"(v));
}
__device__ __forceinline__ u64 fma2(u64 a, u64 b, u64 c) {
    u64 d; asm("fma.rn.f32x2 %0, %1, %2, %3;" : "=l"(d) : "l"(a), "l"(b), "l"(c)); return d;
}

// Paired asin via A&S 4.4.46 (|err|<=2e-8): asin(t) = pi/2 - sqrt(1-t)*P7(t).
__device__ __forceinline__ void asin2_fast(float xa, float xb, float& ra, float& rb) {
    float ta = fminf(fabsf(xa), 1.0f);
    float tb = fminf(fabsf(xb), 1.0f);
    float sa = 1.0f - ta;
    float sb = 1.0f - tb;

    u64 t2 = pk2(ta, tb);
    u64 p  = pk2(-0.0012624911f, -0.0012624911f);
    p = fma2(p, t2, pk2( 0.0066700901f,  0.0066700901f));
    p = fma2(p, t2, pk2(-0.0170881256f, -0.0170881256f));
    p = fma2(p, t2, pk2( 0.0308918810f,  0.0308918810f));
    p = fma2(p, t2, pk2(-0.0501743046f, -0.0501743046f));
    p = fma2(p, t2, pk2( 0.0889789874f,  0.0889789874f));
    p = fma2(p, t2, pk2(-0.2145988016f, -0.2145988016f));
    p = fma2(p, t2, pk2( 1.5707963050f,  1.5707963050f));

    float pa, pb;
    upk2(p, pa, pb);
    float qa = fmaf(sqrt_a(sa), -pa, 1.5707963267948966f);
    float qb = fmaf(sqrt_a(sb), -pb, 1.5707963267948966f);
    ra = copysignf(qa, xa);
    rb = copysignf(qb, xb);
}

// One cell using g = x[j+1]-x[j]:
//   e1 = e0+g, e3 = e2+g  =>  u0 = e0 x g,  u2 = g x e2,  u3 = e2 x e0,
//   u1 = e1 x e3 = u0 + u2 - u3   (cross replaced by adds; e3 never built).
// Carry from cell (i-1,j): e0 = prev e2; u0reg = prev u2 == -(true u0);
// r0 = prev r2. Negations fold into t01/t30 via asin oddness and the sign mask.
template<bool FIRST>
__device__ __forceinline__ float cell_wr(
    float4 P0, float4 P1, F3 g, float4 P2,
    F3& ce2, F3& cu2, float& cr2)
{
    F3 e0;
    if (FIRST) e0 = f3sub(P2, P0);
    else       e0 = ce2;
    F3 e2 = f3sub(P2, P1);

    F3 u0; float r0;
    if (FIRST) {
        u0 = f3cross(e0, g);
        r0 = rsqrt_a(f3dot(u0, u0));
    } else {
        u0 = cu2;            // == -(true u0)
        r0 = cr2;
    }

    F3 u2 = f3cross(g, e2);
    F3 u3 = f3cross(e2, e0);

    F3 u1; // true u1 = u0_true + u2 - u3
    if (FIRST) u1 = { u0.x + u2.x - u3.x, u0.y + u2.y - u3.y, u0.z + u2.z - u3.z };
    else       u1 = { u2.x - u3.x - u0.x, u2.y - u3.y - u0.y, u2.z - u3.z - u0.z };

    float r1 = rsqrt_a(f3dot(u1, u1));
    float r2 = rsqrt_a(f3dot(u2, u2));
    float r3 = rsqrt_a(f3dot(u3, u3));

    float d01 = f3dot(u0, u1);
    float d12 = f3dot(u1, u2);
    float d23 = f3dot(u2, u3);
    float d30 = f3dot(u3, u0);

    float t01, t30;
    if (FIRST) {
        t01 = d01 * (r0 * r1);
        t30 = d30 * (r3 * r0);
    } else {
        t01 = -(d01 * (r0 * r1));
        t30 = -(d30 * (r3 * r0));
    }
    float t12 = d12 * (r1 * r2);
    float t23 = d23 * (r2 * r3);

    float a01, a12, a23, a30;
    asin2_fast(t01, t12, a01, a12);
    asin2_fast(t23, t30, a23, a30);
    float om = ((a01 + a12) + (a23 + a30)) * INV2PI;

    // true sv = -(u0_true . e2); carried u0reg is already negated.
    float dsv = f3dot(u0, e2);
    unsigned smask;
    if (FIRST)
        smask = (__float_as_uint(dsv) ^ 0x80000000u) & 0x80000000u;
    else
        smask = __float_as_uint(dsv) & 0x80000000u;
    float wr = __uint_as_float(__float_as_uint(om) ^ smask);

    ce2 = e2; cu2 = u2; cr2 = r2;
    return wr;
}

// Segment set: {(i,j): 0<=i<=509, i+2<=j<=510}. Final scatter state:
// every (i,j) owns out[i+1][j+1] (+mirror); i==0 also keeps out[0][j] (+mirror).
// Never-written cells (|r-c|<=1 band, (0,511),(511,0)) zeroed by diagonal tiles.
// 128 threads/block: lane tx = j offset, warp ty (0..3) covers 8 consecutive i.
__global__ __launch_bounds__(128) void writhe_tile_kernel(
    const float* __restrict__ x,
    float*       __restrict__ out)
{
    __shared__ float4 si[33];
    __shared__ float4 sj4[33];
    __shared__ float  smwr[32][33];

    // Closed-form decode of k -> (ti, tj), row ti has 16-ti entries.
    // Row start C(ti) = ti*(33-ti)/2.
    const int k = blockIdx.x;
    int ti = (int)((33.0f - sqrtf((float)(1089 - 8 * k))) * 0.5f);
    if (k < ti * (33 - ti) / 2) ti--;                       // fixup for fp boundary
    else if (k >= (ti + 1) * (32 - ti) / 2) ti++;
    const int tj = ti + (k - ti * (33 - ti) / 2);
    const int i0 = ti * 32, j0 = tj * 32;
    const bool fastTile = (ti >= 1) && (tj >= ti + 2) && (tj <= 14);

    const int b = blockIdx.y;
    const float* xb = x + (size_t)b * (NATOMS * 3);
    float* ob = out + (size_t)b * NN;

    const int tx = threadIdx.x & 31;
    const int ty = threadIdx.x >> 5;    // 0..3

    {
        int t = threadIdx.x;
        if (t < 66) {
            int local = (t < 33) ? t : t - 33;
            int c = min(((t < 33) ? i0 : j0) + local, NATOMS - 1);
            float4 v = make_float4(xb[3 * c], xb[3 * c + 1], xb[3 * c + 2], 0.f);
            if (t < 33) si[local] = v; else sj4[local] = v;
        }
    }
    if (ty == 1 && ti == tj) {
        int r = i0 + tx;
        ob[r * 513] = 0.f;
        if (r < NATOMS - 1) { ob[r * 513 + 1] = 0.f; ob[r * 513 + 512] = 0.f; }
        if (ti == 0 && tx == 0) { ob[NATOMS - 1] = 0.f; ob[(NATOMS - 1) * NATOMS] = 0.f; }
    }
    __syncthreads();

    const int j = j0 + tx;
    const float4 P2 = sj4[tx];
    const float4 P3 = sj4[tx + 1];
    const F3 g = f3sub(P3, P2);          // x[j+1]-x[j], per-thread constant
    const int ibase = 8 * ty;            // 8 consecutive i per thread

    F3 ce2, cu2;
    float cr2;
    float wrv[8];

    #pragma unroll
    for (int kk = 0; kk < 8; kk++) {
        const int ii = ibase + kk;
        const float4 P0 = si[ii];
        const float4 P1 = si[ii + 1];
        float wr = (kk == 0)
            ? cell_wr<true >(P0, P1, g, P2, ce2, cu2, cr2)
            : cell_wr<false>(P0, P1, g, P2, ce2, cu2, cr2);
        smwr[ii][tx] = wr;
        wrv[kk] = wr;
    }

    if (fastTile) {
        float* orow = ob + (size_t)(i0 + ibase + 1) * NATOMS + (j + 1);
        #pragma unroll
        for (int kk = 0; kk < 8; kk++)
            orow[kk * NATOMS] = wrv[kk];
    } else {
        #pragma unroll
        for (int kk = 0; kk < 8; kk++) {
            const int i = i0 + ibase + kk;
            bool valid = (j >= i + 2) && (i <= NATOMS - 3) && (j <= NATOMS - 2);
            if (valid) {
                ob[(i + 1) * NATOMS + (j + 1)] = wrv[kk];
                if (i == 0) {
                    ob[j] = wrv[kk];              // (0, j) first-scatter survivor
                    ob[j * NATOMS] = wrv[kk];     // (j, 0)
                }
            }
        }
    }
    __syncthreads();

    // Mirror: coalesced out[j+1][i+1] via transposed smem reads (stride 33).
    if (fastTile) {
        float* ocol = ob + (size_t)(j0 + ibase + 1) * NATOMS + (i0 + tx + 1);
        #pragma unroll
        for (int kk = 0; kk < 8; kk++)
            ocol[kk * NATOMS] = smwr[tx][ibase + kk];
    } else {
        #pragma unroll
        for (int kk = 0; kk < 8; kk++) {
            const int jj = ibase + kk;
            const int jm = j0 + jj;
            const int im = i0 + tx;
            float v = smwr[tx][jj];
            bool valid = (jm >= im + 2) && (im <= NATOMS - 3) && (jm <= NATOMS - 2);
            if (valid)
                ob[(jm + 1) * NATOMS + (im + 1)] = v;
        }
    }
}

extern "C" void kernel_launch(void* const* d_in, const int* in_sizes, int n_in,
                              void* d_out, int out_size)
{
    int xi = (in_sizes[0] == BATCH * NATOMS * 3) ? 0 : 1;
    const float* x   = (const float*)d_in[xi];
    float*       out = (float*)d_out;

    dim3 grid(NTILES, BATCH);
    writhe_tile_kernel<<<grid, 128>>>(x, out);
}